// round 8
// baseline (speedup 1.0000x reference)
#include <cuda_runtime.h>
#include <cstdint>

// EdgeEmbedding — per-edge elementwise (pipeline algebraically collapsed; see R1).
// R8: persistent grid-stride kernel (148*8 blocks, one wave) with double-buffered
// attr smem -> one barrier per tile; otherwise the R7 body: direct stride-3 input
// loads, warp-shuffle emb transpose -> coalesced STG.128, attr staged in smem.

#define SQRT3f  1.7320508075688772f
#define SQRT15f 3.8729833462074170f
#define SQRT5f  2.2360679774997896f
#define SQRT_2_OVER_RC 0.6324555320336759f   // sqrt(2/5)
#define PI_OVER_RC     0.6283185307179586f   // pi/5

#define TILE 256
#define NSM  148
#define BLK_PER_SM 8

__global__ void __launch_bounds__(TILE, BLK_PER_SM)
edge_embedding_kernel(const float* __restrict__ ev,
                      float* __restrict__ out,   // [E | E*8 | E*9]
                      int E, int ntiles)
{
    __shared__ float s_attr[2][9 * TILE];    // 18 KB (double buffer)

    const int t    = threadIdx.x;
    const int lane = t & 31;

    int p = 0;
    for (int tile = blockIdx.x; tile < ntiles; tile += gridDim.x, p ^= 1) {
        const int  base = tile * TILE;
        const bool full = (base + TILE <= E);
        const int  rem  = full ? TILE : (E - base);
        const bool valid = (t < rem);
        float* sa = s_attr[p];

        // ---- direct input load (clamped for tail lanes; L1 caches the lines) ----
        const long long eidx = 3ll * (base + (valid ? t : (rem - 1)));
        const float x = __ldg(&ev[eidx + 0]);
        const float y = __ldg(&ev[eidx + 1]);
        const float z = __ldg(&ev[eidx + 2]);

        const float s    = x * x + y * y + z * z;   // r >= ~0.086 by construction
        const float rinv = rsqrtf(s);
        const float r    = s * rinv;

        if (valid) out[base + t] = r;   // coalesced full-sector STG.32

        // ---- attr to smem first (stride-9 scalar STS, conflict-free) ----
        if (valid) {
            const float ux = x * rinv, uy = y * rinv, uz = z * rinv;
            float* a = sa + 9 * t;
            a[0] = 1.0f;
            a[1] = SQRT3f * ux;
            a[2] = SQRT3f * uy;
            a[3] = SQRT3f * uz;
            a[4] = SQRT15f * ux * uy;
            a[5] = SQRT15f * uy * uz;
            a[6] = 0.5f * SQRT5f * (3.0f * uz * uz - 1.0f);
            a[7] = SQRT15f * ux * uz;
            a[8] = 0.5f * SQRT15f * (ux * ux - uy * uy);
        }

        // ---- poly cutoff p=6: 1 - 28 x^6 + 48 x^7 - 21 x^8 ----
        const float xr = r * 0.2f;
        float env = 0.0f;
        if (xr < 1.0f) {
            const float x2 = xr * xr;
            const float x6 = x2 * x2 * x2;
            env = 1.0f + x6 * (-28.0f + xr * (48.0f - 21.0f * xr));
        }

        // ---- Bessel: sqrt(2/RC)*sin(k*pi*r/RC)/r * env, k=1..8 (Chebyshev) ----
        const float theta = PI_OVER_RC * r;
        float s1, c1;
        __sincosf(theta, &s1, &c1);
        const float pref = SQRT_2_OVER_RC * rinv * env;
        const float tw   = 2.0f * c1;

        float emb[8];
        {
            float sk_m1 = 0.0f, sk = s1;
#pragma unroll
            for (int k = 0; k < 8; ++k) {
                emb[k] = pref * sk;
                const float sk_p1 = tw * sk - sk_m1;
                sk_m1 = sk;
                sk = sk_p1;
            }
        }

        // ---- emb writeout: warp-local transpose via shuffle, coalesced STG.128 ----
        {
            const int warp_base = base + (t & ~31);
            float4* oe = reinterpret_cast<float4*>(out + (size_t)E) + 2ll * warp_base;

            const int srcA = lane >> 1;
            const int srcB = 16 + (lane >> 1);
            const bool hi  = (lane & 1);

            float vA[4], vB[4];
#pragma unroll
            for (int j = 0; j < 4; ++j) {
                const float loA = __shfl_sync(0xffffffffu, emb[j],     srcA);
                const float hiA = __shfl_sync(0xffffffffu, emb[4 + j], srcA);
                vA[j] = hi ? hiA : loA;
            }
#pragma unroll
            for (int j = 0; j < 4; ++j) {
                const float loB = __shfl_sync(0xffffffffu, emb[j],     srcB);
                const float hiB = __shfl_sync(0xffffffffu, emb[4 + j], srcB);
                vB[j] = hi ? hiB : loB;
            }

            if (warp_base + 32 <= E) {
                __stcs(&oe[lane],      make_float4(vA[0], vA[1], vA[2], vA[3]));
                __stcs(&oe[32 + lane], make_float4(vB[0], vB[1], vB[2], vB[3]));
            } else if (valid) {
                float4* oet = reinterpret_cast<float4*>(out + (size_t)E) + 2ll * (base + t);
                oet[0] = make_float4(emb[0], emb[1], emb[2], emb[3]);
                oet[1] = make_float4(emb[4], emb[5], emb[6], emb[7]);
            }
        }

        __syncthreads();   // STS(p) done; also licenses buffer reuse 2 tiles later

        // ---- writeout attr: 9*rem floats as linear float4 (+tail) ----
        const float4* sa4 = reinterpret_cast<const float4*>(sa);
        float4* oa = reinterpret_cast<float4*>(out + 9ll * (size_t)E) +
                     (9ll * base) / 4;        // 9*base % 4 == 0 (base multiple of 256)

        if (full) {
            __stcs(&oa[t],       sa4[t]);
            __stcs(&oa[t + 256], sa4[t + 256]);
            if (t < 64) __stcs(&oa[t + 512], sa4[t + 512]);
        } else {
            float* oat = out + 9ll * (size_t)E + 9ll * base;
            const int nflt = 9 * rem;
            const int n4   = nflt >> 2;
            for (int k = t; k < n4; k += TILE) __stcs(reinterpret_cast<float4*>(oat) + k, sa4[k]);
            for (int k = (n4 << 2) + t; k < nflt; k += TILE) oat[k] = sa[k];
        }
    }
}

extern "C" void kernel_launch(void* const* d_in, const int* in_sizes, int n_in,
                              void* d_out, int out_size)
{
    const float* ev = (const float*)d_in[0];
    const int E = in_sizes[0] / 3;          // 3,000,000 edges

    float* out = (float*)d_out;

    const int ntiles = (E + TILE - 1) / TILE;
    int grid = NSM * BLK_PER_SM;
    if (grid > ntiles) grid = ntiles;
    edge_embedding_kernel<<<grid, TILE>>>(ev, out, E, ntiles);
}

// round 9
// speedup vs baseline: 1.0978x; 1.0978x over previous
#include <cuda_runtime.h>
#include <cstdint>

// EdgeEmbedding — per-edge elementwise (pipeline algebraically collapsed; see R1).
// R9: R7 base, but attr writeout is per-warp (each warp drains its own contiguous
// 288-float smem slice) -> __syncthreads replaced by __syncwarp; warps fully
// independent. Direct stride-3 input loads, warp-shuffle emb transpose ->
// coalesced STG.128, __ldg input / __stcs outputs.

#define SQRT3f  1.7320508075688772f
#define SQRT15f 3.8729833462074170f
#define SQRT5f  2.2360679774997896f
#define SQRT_2_OVER_RC 0.6324555320336759f   // sqrt(2/5)
#define PI_OVER_RC     0.6283185307179586f   // pi/5

#define TILE 256

__global__ void __launch_bounds__(TILE, 8)
edge_embedding_kernel(const float* __restrict__ ev,
                      float* __restrict__ out,   // [E | E*8 | E*9]
                      int E)
{
    __shared__ float s_attr[9 * TILE];       // 9 KB; warp w owns [288w, 288w+288)

    const int  t     = threadIdx.x;
    const int  lane  = t & 31;
    const int  w     = t >> 5;
    const int  base  = blockIdx.x * TILE;
    const int  rem   = min(TILE, E - base);
    const bool valid = (t < rem);

    // ---- direct input load (clamped for tail lanes; L1 caches the lines) ----
    const long long eidx = 3ll * (base + (valid ? t : (rem - 1)));
    const float x = __ldg(&ev[eidx + 0]);
    const float y = __ldg(&ev[eidx + 1]);
    const float z = __ldg(&ev[eidx + 2]);

    const float s    = x * x + y * y + z * z;     // r >= ~0.086 by construction
    const float rinv = rsqrtf(s);
    const float r    = s * rinv;

    if (valid) out[base + t] = r;    // coalesced full-sector STG.32

    // ---- attr to own-warp smem slice (stride-9 scalar STS, conflict-free) ----
    if (valid) {
        const float ux = x * rinv, uy = y * rinv, uz = z * rinv;
        float* a = s_attr + 9 * t;
        a[0] = 1.0f;
        a[1] = SQRT3f * ux;
        a[2] = SQRT3f * uy;
        a[3] = SQRT3f * uz;
        a[4] = SQRT15f * ux * uy;
        a[5] = SQRT15f * uy * uz;
        a[6] = 0.5f * SQRT5f * (3.0f * uz * uz - 1.0f);
        a[7] = SQRT15f * ux * uz;
        a[8] = 0.5f * SQRT15f * (ux * ux - uy * uy);
    }

    // ---- poly cutoff p=6: 1 - 28 x^6 + 48 x^7 - 21 x^8 ----
    const float xr = r * 0.2f;
    float env = 0.0f;
    if (xr < 1.0f) {
        const float x2 = xr * xr;
        const float x6 = x2 * x2 * x2;
        env = 1.0f + x6 * (-28.0f + xr * (48.0f - 21.0f * xr));
    }

    // ---- Bessel: sqrt(2/RC)*sin(k*pi*r/RC)/r * env, k=1..8 (Chebyshev) ----
    const float theta = PI_OVER_RC * r;
    float s1, c1;
    __sincosf(theta, &s1, &c1);
    const float pref = SQRT_2_OVER_RC * rinv * env;
    const float tw   = 2.0f * c1;

    float emb[8];
    {
        float sk_m1 = 0.0f, sk = s1;
#pragma unroll
        for (int k = 0; k < 8; ++k) {
            emb[k] = pref * sk;
            const float sk_p1 = tw * sk - sk_m1;
            sk_m1 = sk;
            sk = sk_p1;
        }
    }

    // ---- emb writeout: warp-local transpose via shuffle, coalesced STG.128 ----
    const int warp_base = base + (w << 5);
    {
        float4* oe = reinterpret_cast<float4*>(out + (size_t)E) + 2ll * warp_base;

        const int srcA = lane >> 1;
        const int srcB = 16 + (lane >> 1);
        const bool hi  = (lane & 1);

        float vA[4], vB[4];
#pragma unroll
        for (int j = 0; j < 4; ++j) {
            const float loA = __shfl_sync(0xffffffffu, emb[j],     srcA);
            const float hiA = __shfl_sync(0xffffffffu, emb[4 + j], srcA);
            vA[j] = hi ? hiA : loA;
        }
#pragma unroll
        for (int j = 0; j < 4; ++j) {
            const float loB = __shfl_sync(0xffffffffu, emb[j],     srcB);
            const float hiB = __shfl_sync(0xffffffffu, emb[4 + j], srcB);
            vB[j] = hi ? hiB : loB;
        }

        if (warp_base + 32 <= E) {
            __stcs(&oe[lane],      make_float4(vA[0], vA[1], vA[2], vA[3]));
            __stcs(&oe[32 + lane], make_float4(vB[0], vB[1], vB[2], vB[3]));
        } else if (valid) {
            // straddling warp (at most one in the grid): scalar fallback
            float4* oet = reinterpret_cast<float4*>(out + (size_t)E) + 2ll * (base + t);
            oet[0] = make_float4(emb[0], emb[1], emb[2], emb[3]);
            oet[1] = make_float4(emb[4], emb[5], emb[6], emb[7]);
        }
    }

    __syncwarp();   // attr STS by this warp now visible to this warp

    // ---- attr writeout: warp drains its OWN 288-float slice, coalesced ----
    if (warp_base + 32 <= E) {
        const float4* sw4 = reinterpret_cast<const float4*>(s_attr) + 72 * w;
        // 9*warp_base % 4 == 0 (warp_base multiple of 32)
        float4* oaw = reinterpret_cast<float4*>(out + 9ll * (size_t)E) +
                      (9ll * warp_base) / 4;
        __stcs(&oaw[lane],      sw4[lane]);
        __stcs(&oaw[32 + lane], sw4[32 + lane]);
        if (lane < 8) __stcs(&oaw[64 + lane], sw4[64 + lane]);
    } else {
        // partial warp: nv valid edges -> 9*nv floats, scalar coalesced drain
        const int nv = rem - (w << 5);
        if (nv > 0) {
            const float* swf = s_attr + 288 * w;
            float* oat = out + 9ll * (size_t)E + 9ll * warp_base;
            const int nflt = 9 * nv;
            for (int k = lane; k < nflt; k += 32) oat[k] = swf[k];
        }
    }
}

extern "C" void kernel_launch(void* const* d_in, const int* in_sizes, int n_in,
                              void* d_out, int out_size)
{
    const float* ev = (const float*)d_in[0];
    const int E = in_sizes[0] / 3;          // 3,000,000 edges

    float* out = (float*)d_out;

    const int blocks = (E + TILE - 1) / TILE;
    edge_embedding_kernel<<<blocks, TILE>>>(ev, out, E);
}

// round 10
// speedup vs baseline: 1.1308x; 1.0301x over previous
#include <cuda_runtime.h>
#include <cstdint>

// EdgeEmbedding — per-edge elementwise (pipeline algebraically collapsed; see R1).
// R10: 2 edges/thread (TILE=512), both edges' inputs loaded up-front (2x MLP),
// then per-group compute + warp-shuffle emb transpose -> coalesced STG.128;
// attr staged in smem, block-wide coalesced drain after one __syncthreads.

#define SQRT3f  1.7320508075688772f
#define SQRT15f 3.8729833462074170f
#define SQRT5f  2.2360679774997896f
#define SQRT_2_OVER_RC 0.6324555320336759f   // sqrt(2/5)
#define PI_OVER_RC     0.6283185307179586f   // pi/5

#define NT   256
#define TILE 512

__global__ void __launch_bounds__(NT, 6)
edge_embedding_kernel(const float* __restrict__ ev,
                      float* __restrict__ out,   // [E | E*8 | E*9]
                      int E)
{
    __shared__ float s_attr[9 * TILE];       // 18 KB

    const int  t     = threadIdx.x;
    const int  lane  = t & 31;
    const int  base  = blockIdx.x * TILE;
    const int  rem   = min(TILE, E - base);

    const int  e0 = base + t;            // group 0: edges [base, base+256)
    const int  e1 = base + NT + t;       // group 1: edges [base+256, base+512)
    const bool v0 = (t < rem);
    const bool v1 = (NT + t < rem);

    // ---- front-batched loads: 6 independent LDGs in flight ----
    const long long i0 = 3ll * (v0 ? e0 : base);
    const long long i1 = 3ll * (v1 ? e1 : base);
    const float x0 = __ldg(&ev[i0 + 0]);
    const float y0 = __ldg(&ev[i0 + 1]);
    const float z0 = __ldg(&ev[i0 + 2]);
    const float x1 = __ldg(&ev[i1 + 0]);
    const float y1 = __ldg(&ev[i1 + 1]);
    const float z1 = __ldg(&ev[i1 + 2]);

#pragma unroll
    for (int g = 0; g < 2; ++g) {
        const float x = g ? x1 : x0;
        const float y = g ? y1 : y0;
        const float z = g ? z1 : z0;
        const bool  valid = g ? v1 : v0;
        const int   e     = g ? e1 : e0;
        const int   slot  = g ? (NT + t) : t;     // attr smem slot

        const float s    = x * x + y * y + z * z;   // r >= ~0.086 by construction
        const float rinv = rsqrtf(s);
        const float r    = s * rinv;

        if (valid) out[e] = r;     // coalesced full-sector STG.32

        // attr to smem (stride-9 scalar STS, conflict-free)
        if (valid) {
            const float ux = x * rinv, uy = y * rinv, uz = z * rinv;
            float* a = s_attr + 9 * slot;
            a[0] = 1.0f;
            a[1] = SQRT3f * ux;
            a[2] = SQRT3f * uy;
            a[3] = SQRT3f * uz;
            a[4] = SQRT15f * ux * uy;
            a[5] = SQRT15f * uy * uz;
            a[6] = 0.5f * SQRT5f * (3.0f * uz * uz - 1.0f);
            a[7] = SQRT15f * ux * uz;
            a[8] = 0.5f * SQRT15f * (ux * ux - uy * uy);
        }

        // poly cutoff p=6: 1 - 28 x^6 + 48 x^7 - 21 x^8
        const float xr = r * 0.2f;
        float env = 0.0f;
        if (xr < 1.0f) {
            const float x2 = xr * xr;
            const float x6 = x2 * x2 * x2;
            env = 1.0f + x6 * (-28.0f + xr * (48.0f - 21.0f * xr));
        }

        // Bessel: sqrt(2/RC)*sin(k*pi*r/RC)/r * env, k=1..8 (Chebyshev)
        const float theta = PI_OVER_RC * r;
        float s1, c1;
        __sincosf(theta, &s1, &c1);
        const float pref = SQRT_2_OVER_RC * rinv * env;
        const float tw   = 2.0f * c1;

        float emb[8];
        {
            float sk_m1 = 0.0f, sk = s1;
#pragma unroll
            for (int k = 0; k < 8; ++k) {
                emb[k] = pref * sk;
                const float sk_p1 = tw * sk - sk_m1;
                sk_m1 = sk;
                sk = sk_p1;
            }
        }

        // emb writeout: warp-local shuffle transpose, coalesced STG.128.
        // Warp owns 32 consecutive edges of this group.
        {
            const int warp_base = (g ? base + NT : base) + (t & ~31);
            float4* oe = reinterpret_cast<float4*>(out + (size_t)E) + 2ll * warp_base;

            const int srcA = lane >> 1;
            const int srcB = 16 + (lane >> 1);
            const bool hi  = (lane & 1);

            float vA[4], vB[4];
#pragma unroll
            for (int j = 0; j < 4; ++j) {
                const float loA = __shfl_sync(0xffffffffu, emb[j],     srcA);
                const float hiA = __shfl_sync(0xffffffffu, emb[4 + j], srcA);
                vA[j] = hi ? hiA : loA;
            }
#pragma unroll
            for (int j = 0; j < 4; ++j) {
                const float loB = __shfl_sync(0xffffffffu, emb[j],     srcB);
                const float hiB = __shfl_sync(0xffffffffu, emb[4 + j], srcB);
                vB[j] = hi ? hiB : loB;
            }

            if (warp_base + 32 <= E) {
                __stcs(&oe[lane],      make_float4(vA[0], vA[1], vA[2], vA[3]));
                __stcs(&oe[32 + lane], make_float4(vB[0], vB[1], vB[2], vB[3]));
            } else if (valid) {
                float4* oet = reinterpret_cast<float4*>(out + (size_t)E) + 2ll * e;
                oet[0] = make_float4(emb[0], emb[1], emb[2], emb[3]);
                oet[1] = make_float4(emb[4], emb[5], emb[6], emb[7]);
            }
        }
    }

    __syncthreads();

    // ---- writeout attr: 9*rem floats as linear float4 (+tail) ----
    const float4* sa4 = reinterpret_cast<const float4*>(s_attr);
    float4* oa = reinterpret_cast<float4*>(out + 9ll * (size_t)E) +
                 (9ll * base) / 4;           // 9*base % 4 == 0 (base multiple of 512)

    if (rem == TILE) {
        // 9*512/4 = 1152 float4 = 4.5 rounds of 256 threads
        __stcs(&oa[t],        sa4[t]);
        __stcs(&oa[t + 256],  sa4[t + 256]);
        __stcs(&oa[t + 512],  sa4[t + 512]);
        __stcs(&oa[t + 768],  sa4[t + 768]);
        if (t < 128) __stcs(&oa[t + 1024], sa4[t + 1024]);
    } else {
        float* oat = out + 9ll * (size_t)E + 9ll * base;
        const int nflt = 9 * rem;
        const int n4   = nflt >> 2;
        for (int k = t; k < n4; k += NT) __stcs(reinterpret_cast<float4*>(oat) + k, sa4[k]);
        for (int k = (n4 << 2) + t; k < nflt; k += NT) oat[k] = s_attr[k];
    }
}

extern "C" void kernel_launch(void* const* d_in, const int* in_sizes, int n_in,
                              void* d_out, int out_size)
{
    const float* ev = (const float*)d_in[0];
    const int E = in_sizes[0] / 3;          // 3,000,000 edges

    float* out = (float*)d_out;

    const int blocks = (E + TILE - 1) / TILE;
    edge_embedding_kernel<<<blocks, NT>>>(ev, out, E);
}